// round 16
// baseline (speedup 1.0000x reference)
#include <cuda_runtime.h>
#include <math.h>

// Problem constants
#define NN 100000
#define EE 1280000
#define FDIM 64
#define CDIM 40

// Scratch (static __device__ globals: no allocation allowed)
__device__ int   g_is64;
__device__ int   g_deg[NN];
__device__ int   g_cur[NN];
__device__ int   g_off[NN + 1];
__device__ float g_dinv[NN];
__device__ int2  g_csr[EE];                    // {src, bitcast(weight)}
__device__ float g_h0[(size_t)NN * FDIM];
__device__ float g_h1[(size_t)NN * FDIM];

// ---------------------------------------------------------------------------
// Detect whether edge_index is int64 or int32. With int64 data (values <
// 100000 << 2^31) every odd 32-bit word is a zero high-word; with genuine
// int32 random indices that is (prob ~0) never true for 256 samples.
__global__ void k_detect(const int* __restrict__ ei32) {
    int any = 0;
    for (int i = 1; i < 512; i += 2) any |= ei32[i];
    g_is64 = (any == 0) ? 1 : 0;
}

__device__ __forceinline__ int edge_at(const void* ei, size_t idx, int is64) {
    if (is64) return (int)((const long long*)ei)[idx];
    return ((const int*)ei)[idx];
}

__global__ void k_zero(int n) {
    int i = blockIdx.x * blockDim.x + threadIdx.x;
    if (i < n) { g_deg[i] = 0; g_cur[i] = 0; }
}

// in-degree of real edges (self loops handled analytically: deg = in_deg + 1)
__global__ void k_count(const void* __restrict__ ei, int E) {
    int is64 = g_is64;
    int e = blockIdx.x * blockDim.x + threadIdx.x;
    if (e < E) {
        int d = edge_at(ei, (size_t)E + e, is64);
        atomicAdd(&g_deg[d], 1);
    }
}

__global__ void k_dinv(int n) {
    int i = blockIdx.x * blockDim.x + threadIdx.x;
    if (i < n) g_dinv[i] = rsqrtf((float)g_deg[i] + 1.0f);
}

// Single-block exclusive scan of g_deg -> g_off
__global__ void k_scan(int n) {
    const int T = 1024;
    int tid = threadIdx.x;
    int per = (n + T - 1) / T;
    int s0 = tid * per;
    int s1 = min(s0 + per, n);
    int sum = 0;
    for (int i = s0; i < s1; i++) sum += g_deg[i];
    __shared__ int sh[T];
    sh[tid] = sum;
    __syncthreads();
    for (int off = 1; off < T; off <<= 1) {
        int v = 0;
        if (tid >= off) v = sh[tid - off];
        __syncthreads();
        sh[tid] += v;
        __syncthreads();
    }
    int run = (tid == 0) ? 0 : sh[tid - 1];
    for (int i = s0; i < s1; i++) { g_off[i] = run; run += g_deg[i]; }
    if (tid == T - 1) g_off[n] = run;   // = E
}

// Fill CSR: slot each edge under its dst; pack src + precomputed weight.
__global__ void k_fill(const void* __restrict__ ei, int E) {
    int is64 = g_is64;
    int e = blockIdx.x * blockDim.x + threadIdx.x;
    if (e < E) {
        int s = edge_at(ei, (size_t)e, is64);
        int d = edge_at(ei, (size_t)E + e, is64);
        int pos = g_off[d] + atomicAdd(&g_cur[d], 1);
        float w = g_dinv[s] * g_dinv[d];
        g_csr[pos] = make_int2(s, __float_as_int(w));
    }
}

// One propagation hop: h_out[v] = dinv[v]^2*h_in[v] + sum_in-edges w*h_in[src]
// Warp per node; lane owns 2 features (float2 => coalesced 256B per edge).
// mode 0: x -> g_h1 ; mode 1: g_h1 -> g_h0 ; mode 2: g_h0 -> g_h1
__global__ void k_gather(int mode, const float* __restrict__ x, int n) {
    int w = (blockIdx.x * blockDim.x + threadIdx.x) >> 5;
    int lane = threadIdx.x & 31;
    if (w >= n) return;

    const float* __restrict__ hin = (mode == 0) ? x : ((mode == 1) ? g_h1 : g_h0);
    float* __restrict__ hout = (mode == 1) ? g_h0 : g_h1;

    float di = g_dinv[w];
    float2 hv = ((const float2*)(hin + (size_t)w * FDIM))[lane];
    float ax = di * di * hv.x;
    float ay = di * di * hv.y;

    int beg = g_off[w], end = g_off[w + 1];
    int j = beg;
    for (; j + 1 < end; j += 2) {
        int2 e0 = g_csr[j];
        int2 e1 = g_csr[j + 1];
        float2 a = __ldg((const float2*)(hin + (size_t)e0.x * FDIM) + lane);
        float2 b = __ldg((const float2*)(hin + (size_t)e1.x * FDIM) + lane);
        float w0 = __int_as_float(e0.y);
        float w1 = __int_as_float(e1.y);
        ax += w0 * a.x; ay += w0 * a.y;
        ax += w1 * b.x; ay += w1 * b.y;
    }
    if (j < end) {
        int2 e0 = g_csr[j];
        float2 a = __ldg((const float2*)(hin + (size_t)e0.x * FDIM) + lane);
        float w0 = __int_as_float(e0.y);
        ax += w0 * a.x; ay += w0 * a.y;
    }
    ((float2*)(hout + (size_t)w * FDIM))[lane] = make_float2(ax, ay);
}

// Fused linear (h @ W^T + b) + log_softmax. Thread per node.
__global__ void k_out(const float* __restrict__ W,
                      const float* __restrict__ b,
                      float* __restrict__ out, int n) {
    __shared__ float4 sW[CDIM * (FDIM / 4)];
    __shared__ float sb[CDIM];
    for (int i = threadIdx.x; i < CDIM * (FDIM / 4); i += blockDim.x)
        sW[i] = ((const float4*)W)[i];
    if (threadIdx.x < CDIM) sb[threadIdx.x] = b[threadIdx.x];
    __syncthreads();

    int v = blockIdx.x * blockDim.x + threadIdx.x;
    if (v >= n) return;

    float logit[CDIM];
#pragma unroll
    for (int c = 0; c < CDIM; c++) logit[c] = sb[c];

    const float4* hr = (const float4*)(g_h1 + (size_t)v * FDIM);
#pragma unroll
    for (int q = 0; q < FDIM / 4; q++) {
        float4 hv = __ldg(hr + q);
#pragma unroll
        for (int c = 0; c < CDIM; c++) {
            float4 wv = sW[c * (FDIM / 4) + q];
            logit[c] += hv.x * wv.x + hv.y * wv.y + hv.z * wv.z + hv.w * wv.w;
        }
    }

    float m = logit[0];
#pragma unroll
    for (int c = 1; c < CDIM; c++) m = fmaxf(m, logit[c]);
    float s = 0.0f;
#pragma unroll
    for (int c = 0; c < CDIM; c++) s += expf(logit[c] - m);
    float lse = m + logf(s);

    float4* o = (float4*)(out + (size_t)v * CDIM);
#pragma unroll
    for (int q = 0; q < CDIM / 4; q++) {
        o[q] = make_float4(logit[4 * q + 0] - lse, logit[4 * q + 1] - lse,
                           logit[4 * q + 2] - lse, logit[4 * q + 3] - lse);
    }
}

// ---------------------------------------------------------------------------
extern "C" void kernel_launch(void* const* d_in, const int* in_sizes, int n_in,
                              void* d_out, int out_size) {
    const float* x   = (const float*)d_in[0];   // [N,64] f32
    const void*  ei  = d_in[1];                 // [2,E] i32 or i64
    const float* W   = (const float*)d_in[2];   // [40,64] f32
    const float* b   = (const float*)d_in[3];   // [40] f32
    float*       out = (float*)d_out;           // [N,40] f32

    int N = in_sizes[0] / FDIM;   // 100000
    int E = in_sizes[1] / 2;      // 1280000

    const int TB = 256;
    k_detect<<<1, 1>>>((const int*)ei);
    k_zero <<<(N + TB - 1) / TB, TB>>>(N);
    k_count<<<(E + TB - 1) / TB, TB>>>(ei, E);
    k_dinv <<<(N + TB - 1) / TB, TB>>>(N);
    k_scan <<<1, 1024>>>(N);
    k_fill <<<(E + TB - 1) / TB, TB>>>(ei, E);

    int gblocks = (N * 32 + TB - 1) / TB;   // warp per node
    k_gather<<<gblocks, TB>>>(0, x, N);     // x    -> g_h1
    k_gather<<<gblocks, TB>>>(1, x, N);     // g_h1 -> g_h0
    k_gather<<<gblocks, TB>>>(2, x, N);     // g_h0 -> g_h1

    k_out<<<(N + TB - 1) / TB, TB>>>(W, b, out, N);
}

// round 17
// speedup vs baseline: 1.4687x; 1.4687x over previous
#include <cuda_runtime.h>
#include <math.h>

// Problem constants
#define NN 100000
#define EE 1280000
#define FDIM 64
#define CDIM 40

// Scan config
#define SCAN_T 8192            // total scan threads (32 blocks x 256)
#define SCAN_CHUNK 13          // ceil(NN / SCAN_T)

// Scratch (static __device__ globals: no allocation allowed)
__device__ int    g_is64;
__device__ int    g_deg[NN];
__device__ int    g_cur[NN];
__device__ int    g_off[NN + 1];
__device__ float  g_dinv[NN];
__device__ int    g_part[SCAN_T];
__device__ int2   g_csr[EE];                         // {src, bitcast(weight)}
__device__ float4 g_y0[(size_t)NN * (CDIM / 4)];     // [N,40] projected feats
__device__ float4 g_y1[(size_t)NN * (CDIM / 4)];

// ---------------------------------------------------------------------------
// Zero counters; block 0 / thread 0 also detects int64 vs int32 edge_index
// (int64 values < 1e5 => every odd 32-bit word is a zero high-word).
__global__ void k_zero(const int* __restrict__ ei32, int n) {
    int i = blockIdx.x * blockDim.x + threadIdx.x;
    if (i < n) { g_deg[i] = 0; g_cur[i] = 0; }
    if (i == 0) {
        int any = 0;
        for (int k = 1; k < 512; k += 2) any |= ei32[k];
        g_is64 = (any == 0) ? 1 : 0;
    }
}

__device__ __forceinline__ int edge_at(const void* ei, size_t idx, int is64) {
    if (is64) return (int)((const long long*)ei)[idx];
    return ((const int*)ei)[idx];
}

// in-degree of real edges (self loop handled analytically: deg = in_deg + 1)
__global__ void k_count(const void* __restrict__ ei, int E) {
    int is64 = g_is64;
    int e = blockIdx.x * blockDim.x + threadIdx.x;
    if (e < E) atomicAdd(&g_deg[edge_at(ei, (size_t)E + e, is64)], 1);
}

// Scan phase 1: per-thread chunk sums (also computes dinv, fused)
__global__ void k_scan1(int n) {
    int t = blockIdx.x * blockDim.x + threadIdx.x;   // 0..SCAN_T-1
    int s0 = t * SCAN_CHUNK, s1 = min(s0 + SCAN_CHUNK, n);
    int sum = 0;
    for (int i = s0; i < s1; i++) {
        int d = g_deg[i];
        sum += d;
        g_dinv[i] = rsqrtf((float)d + 1.0f);
    }
    g_part[t] = sum;
}

// Scan phase 2: single block, exclusive scan of the 8192 partials
__global__ void k_scan2() {
    const int T = 1024;
    int t = threadIdx.x;
    int loc[8]; int sum = 0;
#pragma unroll
    for (int i = 0; i < 8; i++) { loc[i] = g_part[t * 8 + i]; sum += loc[i]; }
    __shared__ int sh[T];
    sh[t] = sum;
    __syncthreads();
    for (int off = 1; off < T; off <<= 1) {
        int v = 0;
        if (t >= off) v = sh[t - off];
        __syncthreads();
        sh[t] += v;
        __syncthreads();
    }
    int run = (t == 0) ? 0 : sh[t - 1];
#pragma unroll
    for (int i = 0; i < 8; i++) { g_part[t * 8 + i] = run; run += loc[i]; }
}

// Scan phase 3: write per-element exclusive offsets
__global__ void k_scan3(int n) {
    int t = blockIdx.x * blockDim.x + threadIdx.x;
    int s0 = t * SCAN_CHUNK, s1 = min(s0 + SCAN_CHUNK, n);
    int run = g_part[t];
    for (int i = s0; i < s1; i++) { g_off[i] = run; run += g_deg[i]; }
    if (s0 < n && s1 == n) g_off[n] = run;   // = E
}

// Fill CSR: slot each edge under its dst; pack src + precomputed weight.
__global__ void k_fill(const void* __restrict__ ei, int E) {
    int is64 = g_is64;
    int e = blockIdx.x * blockDim.x + threadIdx.x;
    if (e < E) {
        int s = edge_at(ei, (size_t)e, is64);
        int d = edge_at(ei, (size_t)E + e, is64);
        int pos = g_off[d] + atomicAdd(&g_cur[d], 1);
        float w = g_dinv[s] * g_dinv[d];
        g_csr[pos] = make_int2(s, __float_as_int(w));
    }
}

// Projection first (linearity: P^3(xW^T) = (P^3 x)W^T). Thread per node.
__global__ void k_mlp(const float* __restrict__ x,
                      const float* __restrict__ W, int n) {
    __shared__ float4 sW[CDIM * (FDIM / 4)];
    for (int i = threadIdx.x; i < CDIM * (FDIM / 4); i += blockDim.x)
        sW[i] = ((const float4*)W)[i];
    __syncthreads();

    int v = blockIdx.x * blockDim.x + threadIdx.x;
    if (v >= n) return;

    float acc[CDIM];
#pragma unroll
    for (int c = 0; c < CDIM; c++) acc[c] = 0.0f;

    const float4* xr = (const float4*)(x + (size_t)v * FDIM);
#pragma unroll
    for (int q = 0; q < FDIM / 4; q++) {
        float4 hv = __ldg(xr + q);
#pragma unroll
        for (int c = 0; c < CDIM; c++) {
            float4 wv = sW[c * (FDIM / 4) + q];
            acc[c] += hv.x * wv.x + hv.y * wv.y + hv.z * wv.z + hv.w * wv.w;
        }
    }
    float4* o = g_y0 + (size_t)v * (CDIM / 4);
#pragma unroll
    for (int q = 0; q < CDIM / 4; q++)
        o[q] = make_float4(acc[4 * q], acc[4 * q + 1], acc[4 * q + 2], acc[4 * q + 3]);
}

// One propagation hop over 40-dim features.
// Warp per node; lanes 0..19 each own a float2 (contiguous 160B = 5 sectors).
// mode 0: g_y0 -> g_y1 ; mode 1: g_y1 -> g_y0
__global__ void k_gather(int mode, int n) {
    int w = (blockIdx.x * blockDim.x + threadIdx.x) >> 5;
    int lane = threadIdx.x & 31;
    if (w >= n || lane >= CDIM / 2) return;

    const float2* __restrict__ hin =
        (mode == 0) ? (const float2*)g_y0 : (const float2*)g_y1;
    float2* __restrict__ hout = (mode == 0) ? (float2*)g_y1 : (float2*)g_y0;

    float di = g_dinv[w];
    float2 hv = hin[(size_t)w * (CDIM / 2) + lane];
    float ax = di * di * hv.x;
    float ay = di * di * hv.y;

    int beg = g_off[w], end = g_off[w + 1];
    int j = beg;
    for (; j + 3 < end; j += 4) {
        int2 e0 = g_csr[j];
        int2 e1 = g_csr[j + 1];
        int2 e2 = g_csr[j + 2];
        int2 e3 = g_csr[j + 3];
        float2 a = __ldg(hin + (size_t)e0.x * (CDIM / 2) + lane);
        float2 b = __ldg(hin + (size_t)e1.x * (CDIM / 2) + lane);
        float2 c = __ldg(hin + (size_t)e2.x * (CDIM / 2) + lane);
        float2 d = __ldg(hin + (size_t)e3.x * (CDIM / 2) + lane);
        float w0 = __int_as_float(e0.y), w1 = __int_as_float(e1.y);
        float w2 = __int_as_float(e2.y), w3 = __int_as_float(e3.y);
        ax += w0 * a.x; ay += w0 * a.y;
        ax += w1 * b.x; ay += w1 * b.y;
        ax += w2 * c.x; ay += w2 * c.y;
        ax += w3 * d.x; ay += w3 * d.y;
    }
    for (; j < end; j++) {
        int2 e0 = g_csr[j];
        float2 a = __ldg(hin + (size_t)e0.x * (CDIM / 2) + lane);
        float w0 = __int_as_float(e0.y);
        ax += w0 * a.x; ay += w0 * a.y;
    }
    hout[(size_t)w * (CDIM / 2) + lane] = make_float2(ax, ay);
}

// Bias + log_softmax over [N, 40]. Thread per node, reads g_y1.
__global__ void k_lsm(const float* __restrict__ b, float* __restrict__ out, int n) {
    __shared__ float sb[CDIM];
    if (threadIdx.x < CDIM) sb[threadIdx.x] = b[threadIdx.x];
    __syncthreads();

    int v = blockIdx.x * blockDim.x + threadIdx.x;
    if (v >= n) return;

    float l[CDIM];
    const float4* yr = g_y1 + (size_t)v * (CDIM / 4);
#pragma unroll
    for (int q = 0; q < CDIM / 4; q++) {
        float4 t = __ldg(yr + q);
        l[4 * q + 0] = t.x + sb[4 * q + 0];
        l[4 * q + 1] = t.y + sb[4 * q + 1];
        l[4 * q + 2] = t.z + sb[4 * q + 2];
        l[4 * q + 3] = t.w + sb[4 * q + 3];
    }
    float m = l[0];
#pragma unroll
    for (int c = 1; c < CDIM; c++) m = fmaxf(m, l[c]);
    float s = 0.0f;
#pragma unroll
    for (int c = 0; c < CDIM; c++) s += expf(l[c] - m);
    float lse = m + logf(s);

    float4* o = (float4*)(out + (size_t)v * CDIM);
#pragma unroll
    for (int q = 0; q < CDIM / 4; q++)
        o[q] = make_float4(l[4 * q + 0] - lse, l[4 * q + 1] - lse,
                           l[4 * q + 2] - lse, l[4 * q + 3] - lse);
}

// ---------------------------------------------------------------------------
extern "C" void kernel_launch(void* const* d_in, const int* in_sizes, int n_in,
                              void* d_out, int out_size) {
    const float* x   = (const float*)d_in[0];   // [N,64] f32
    const void*  ei  = d_in[1];                 // [2,E] i32 or i64
    const float* W   = (const float*)d_in[2];   // [40,64] f32
    const float* b   = (const float*)d_in[3];   // [40] f32
    float*       out = (float*)d_out;           // [N,40] f32

    int N = in_sizes[0] / FDIM;   // 100000
    int E = in_sizes[1] / 2;      // 1280000

    const int TB = 256;
    k_zero <<<(N + TB - 1) / TB, TB>>>((const int*)ei, N);
    k_count<<<(E + TB - 1) / TB, TB>>>(ei, E);
    k_scan1<<<SCAN_T / TB, TB>>>(N);
    k_scan2<<<1, 1024>>>();
    k_scan3<<<SCAN_T / TB, TB>>>(N);
    k_fill <<<(E + TB - 1) / TB, TB>>>(ei, E);

    k_mlp<<<(N + TB - 1) / TB, TB>>>(x, W, N);      // x @ W^T -> g_y0

    int gblocks = (N * 32 + TB - 1) / TB;           // warp per node
    k_gather<<<gblocks, TB>>>(0, N);                // y0 -> y1
    k_gather<<<gblocks, TB>>>(1, N);                // y1 -> y0
    k_gather<<<gblocks, TB>>>(0, N);                // y0 -> y1

    k_lsm<<<(N + TB - 1) / TB, TB>>>(b, out, N);
}